// round 8
// baseline (speedup 1.0000x reference)
#include <cuda_runtime.h>
#include <cuda_bf16.h>
#include <math.h>
#include <stdint.h>

// ---------------- problem constants ----------------
#define NTOK 4096
#define NKV  1024

typedef unsigned short u16;

// ---------------- low-level helpers (compute_103-baseline PTX only) ----------------
__device__ __forceinline__ uint32_t smem_u32(const void* p) {
    uint32_t a;
    asm("{ .reg .u64 t; cvta.to.shared.u64 t, %1; cvt.u32.u64 %0, t; }" : "=r"(a) : "l"(p));
    return a;
}
__device__ __forceinline__ void cp16(uint32_t s, const void* g) {
    asm volatile("cp.async.cg.shared.global [%0], [%1], 16;" :: "r"(s), "l"(g));
}
#define CP_COMMIT() asm volatile("cp.async.commit_group;" ::: "memory")
#define CP_WAIT0()  asm volatile("cp.async.wait_group 0;" ::: "memory")
#define CP_WAIT1()  asm volatile("cp.async.wait_group 1;" ::: "memory")
#define CP_WAIT2()  asm volatile("cp.async.wait_group 2;" ::: "memory")

__device__ __forceinline__ void ldm4(uint32_t* r, uint32_t a) {
    asm volatile("ldmatrix.sync.aligned.m8n8.x4.shared.b16 {%0,%1,%2,%3}, [%4];"
                 : "=r"(r[0]), "=r"(r[1]), "=r"(r[2]), "=r"(r[3]) : "r"(a));
}
__device__ __forceinline__ void ldm4t(uint32_t* r, uint32_t a) {
    asm volatile("ldmatrix.sync.aligned.m8n8.x4.trans.shared.b16 {%0,%1,%2,%3}, [%4];"
                 : "=r"(r[0]), "=r"(r[1]), "=r"(r[2]), "=r"(r[3]) : "r"(a));
}
__device__ __forceinline__ void mmabf(float* d, const uint32_t* a, const uint32_t* b) {
    asm volatile("mma.sync.aligned.m16n8k16.row.col.f32.bf16.bf16.f32 "
                 "{%0,%1,%2,%3}, {%4,%5,%6,%7}, {%8,%9}, {%0,%1,%2,%3};"
                 : "+f"(d[0]), "+f"(d[1]), "+f"(d[2]), "+f"(d[3])
                 : "r"(a[0]), "r"(a[1]), "r"(a[2]), "r"(a[3]), "r"(b[0]), "r"(b[1]));
}

__device__ __forceinline__ ushort2 split_bf(float x) {
    __nv_bfloat16 h = __float2bfloat16(x);
    __nv_bfloat16 l = __float2bfloat16(x - __bfloat162float(h));
    return make_ushort2(__bfloat16_as_ushort(h), __bfloat16_as_ushort(l));
}
__device__ __forceinline__ void split_pack2(float a, float b, uint32_t& rh, uint32_t& rl) {
    __nv_bfloat16 ah = __float2bfloat16(a), bh = __float2bfloat16(b);
    __nv_bfloat16 al = __float2bfloat16(a - __bfloat162float(ah));
    __nv_bfloat16 bl = __float2bfloat16(b - __bfloat162float(bh));
    rh = (uint32_t)__bfloat16_as_ushort(ah) | ((uint32_t)__bfloat16_as_ushort(bh) << 16);
    rl = (uint32_t)__bfloat16_as_ushort(al) | ((uint32_t)__bfloat16_as_ushort(bl) << 16);
}

// ---------------- device scratch ----------------
__device__ u16 g_xp_hi [4096u * 2048u], g_xp_lo [4096u * 2048u];
__device__ u16 g_x_hi  [16384u * 512u], g_x_lo  [16384u * 512u];
__device__ u16 g_kvn_hi[4096u * 512u],  g_kvn_lo[4096u * 512u];
__device__ u16 g_q_hi  [16384u * 512u], g_q_lo  [16384u * 512u];
__device__ u16 g_k_hi  [4096u * 512u],  g_k_lo  [4096u * 512u];
__device__ u16 g_v_hi  [4096u * 512u],  g_v_lo  [4096u * 512u];
__device__ u16 g_ao_hi [16384u * 512u], g_ao_lo [16384u * 512u];
__device__ u16 g_wq_hi [512u * 512u],   g_wq_lo [512u * 512u];
__device__ u16 g_wk_hi [512u * 512u],   g_wk_lo [512u * 512u];
__device__ u16 g_wv_hi [512u * 512u],   g_wv_lo [512u * 512u];
__device__ u16 g_wp_hi [512u * 512u],   g_wp_lo [512u * 512u];
__device__ u16 g_sw_hi [512u * 2048u],  g_sw_lo [512u * 2048u];
__device__ float g_kv[4096u * 512u];

// ---------------- im2col (2x2 stride-2) fused with hi/lo split ----------------
__global__ void __launch_bounds__(256) im2col_hilo(const float* __restrict__ x,
                                                   ushort4* __restrict__ hi,
                                                   ushort4* __restrict__ lo)
{
    int id  = blockIdx.x * blockDim.x + threadIdx.x;   // float4 index, 2097152 total
    int row = id >> 9;
    int k   = (id & 511) * 4;
    int p   = k >> 9, c = k & 511;
    int di  = p >> 1, dj = p & 1;
    int b   = row >> 10, rem = row & 1023;
    int i   = rem >> 5,  j   = rem & 31;
    int srow = b * 4096 + (2 * i + di) * 64 + (2 * j + dj);
    float4 v = reinterpret_cast<const float4*>(x)[(size_t)(srow * 512 + c) >> 2];
    ushort2 a = split_bf(v.x), bb = split_bf(v.y), cc = split_bf(v.z), d = split_bf(v.w);
    hi[id] = make_ushort4(a.x, bb.x, cc.x, d.x);
    lo[id] = make_ushort4(a.y, bb.y, cc.y, d.y);
}

// ---------------- generic fp32 -> hi/lo ----------------
__global__ void __launch_bounds__(256) cvt_hilo(const float4* __restrict__ src,
                                                ushort4* __restrict__ hi,
                                                ushort4* __restrict__ lo, int n4)
{
    int id = blockIdx.x * blockDim.x + threadIdx.x;
    if (id >= n4) return;
    float4 v = src[id];
    ushort2 a = split_bf(v.x), b = split_bf(v.y), c = split_bf(v.z), d = split_bf(v.w);
    hi[id] = make_ushort4(a.x, b.x, c.x, d.x);
    lo[id] = make_ushort4(a.y, b.y, c.y, d.y);
}

// ---------------- weight transpose + hi/lo split: W[K,N] -> T[N,K] ----------------
__global__ void wT_hilo(const float* __restrict__ W,
                        u16* __restrict__ Thi, u16* __restrict__ Tlo, int K, int N)
{
    __shared__ float t[32][33];
    int n0 = blockIdx.x * 32, k0 = blockIdx.y * 32;
    for (int i = threadIdx.y; i < 32; i += 8)
        t[i][threadIdx.x] = W[(size_t)(k0 + i) * N + n0 + threadIdx.x];
    __syncthreads();
    for (int i = threadIdx.y; i < 32; i += 8) {
        ushort2 s = split_bf(t[threadIdx.x][i]);
        size_t o = (size_t)(n0 + i) * K + k0 + threadIdx.x;
        Thi[o] = s.x; Tlo[o] = s.y;
    }
}

// 4 x (512x512) weight transposes in one launch; blockIdx.z selects the tensor.
__global__ void wT4_hilo(const float* __restrict__ W0, const float* __restrict__ W1,
                         const float* __restrict__ W2, const float* __restrict__ W3,
                         u16* __restrict__ H0, u16* __restrict__ L0,
                         u16* __restrict__ H1, u16* __restrict__ L1,
                         u16* __restrict__ H2, u16* __restrict__ L2,
                         u16* __restrict__ H3, u16* __restrict__ L3)
{
    const float* W; u16 *Thi, *Tlo;
    switch (blockIdx.z) {
        case 0:  W = W0; Thi = H0; Tlo = L0; break;
        case 1:  W = W1; Thi = H1; Tlo = L1; break;
        case 2:  W = W2; Thi = H2; Tlo = L2; break;
        default: W = W3; Thi = H3; Tlo = L3; break;
    }
    __shared__ float t[32][33];
    int n0 = blockIdx.x * 32, k0 = blockIdx.y * 32;
    for (int i = threadIdx.y; i < 32; i += 8)
        t[i][threadIdx.x] = W[(size_t)(k0 + i) * 512 + n0 + threadIdx.x];
    __syncthreads();
    for (int i = threadIdx.y; i < 32; i += 8) {
        ushort2 s = split_bf(t[threadIdx.x][i]);
        size_t o = (size_t)(n0 + i) * 512 + k0 + threadIdx.x;
        Thi[o] = s.x; Tlo[o] = s.y;
    }
}

// ---------------- mma.sync bf16 3-term GEMM ----------------
// 128x128 tile, BK=32, 3-stage cp.async pipeline, hi/lo interleaved per 128B row:
// row r of a stage tile = [hi k0..k0+31 (64B) | lo k0..k0+31 (64B)], chunks 0-3 hi, 4-7 lo.
// EPI==0: fp32 row-major C [M,512].  EPI==1: head-major hi/lo scatter (n->h=n%8,d=n/8).
#define GSMEM (3 * 32768 + 1024)

template <int EPI>
__global__ void __launch_bounds__(256, 2) gemm_mma(
    const u16* __restrict__ Ahi, const u16* __restrict__ Alo,
    const u16* __restrict__ Bhi, const u16* __restrict__ Blo,
    const float* __restrict__ bias, float oscale, float* __restrict__ C,
    u16* __restrict__ Chi, u16* __restrict__ Clo, int K, int Ntok)
{
    extern __shared__ char dsm[];
    const int tid = threadIdx.x, lane = tid & 31, wid = tid >> 5;
    const int wm = wid & 3, wn = wid >> 2;
    const int m0 = blockIdx.y * 128, n0 = blockIdx.x * 128;

    uint32_t dyn = smem_u32(dsm);
    uint32_t sb  = (dyn + 1023) & ~1023u;

    const u16* sA0 = Ahi + (size_t)m0 * K;
    const u16* sA1 = Alo + (size_t)m0 * K;
    const u16* sB0 = Bhi + (size_t)n0 * K;
    const u16* sB1 = Blo + (size_t)n0 * K;

    float acc[2][8][4];
#pragma unroll
    for (int a = 0; a < 2; a++)
#pragma unroll
        for (int b = 0; b < 8; b++)
#pragma unroll
            for (int c = 0; c < 4; c++) acc[a][b][c] = 0.f;

    const int NC = K >> 5;   // chunks of 32 k

    auto load_chunk = [&](int i) {
        int kk0 = (i % 3), k0 = i << 5;
        uint32_t bb = sb + kk0 * 32768;
        // A: 128 rows x 8 chunks (0-3 hi, 4-7 lo) = 1024 cp16
#pragma unroll
        for (int it = 0; it < 4; it++) {
            int idx = tid + it * 256;
            int r = idx >> 3, c = idx & 7;
            const u16* src = (c < 4 ? sA0 : sA1) + (size_t)r * K + k0 + (c & 3) * 8;
            cp16(bb + r * 128 + ((c ^ (r & 7)) << 4), src);
        }
        // B: 128 rows x 8 chunks = 1024 cp16
#pragma unroll
        for (int it = 0; it < 4; it++) {
            int idx = tid + it * 256;
            int r = idx >> 3, c = idx & 7;
            const u16* src = (c < 4 ? sB0 : sB1) + (size_t)r * K + k0 + (c & 3) * 8;
            cp16(bb + 16384 + r * 128 + ((c ^ (r & 7)) << 4), src);
        }
        CP_COMMIT();
    };

    load_chunk(0);
    if (NC > 1) load_chunk(1);
    for (int i = 0; i < NC; i++) {
        if (i + 2 < NC) { load_chunk(i + 2); CP_WAIT2(); }
        else if (i + 1 < NC) { CP_WAIT1(); }
        else { CP_WAIT0(); }
        __syncthreads();

        uint32_t base = sb + (i % 3) * 32768;
        uint32_t A = base, B = base + 16384;
#pragma unroll
        for (int ks = 0; ks < 2; ks++) {
            uint32_t ah[2][4], al[2][4];
#pragma unroll
            for (int mt = 0; mt < 2; mt++) {
                int r = wm * 32 + mt * 16 + (lane & 15);
                int u = 2 * ks + (lane >> 4);
                ldm4(ah[mt], A + r * 128 + ((u ^ (r & 7)) << 4));
                ldm4(al[mt], A + r * 128 + (((u + 4) ^ (r & 7)) << 4));
            }
#pragma unroll
            for (int np = 0; np < 4; np++) {
                uint32_t bh[4], bl[4];
                int r = wn * 64 + np * 16 + ((lane >> 4) << 3) + (lane & 7);
                int u = 2 * ks + ((lane >> 3) & 1);
                ldm4(bh, B + r * 128 + ((u ^ (r & 7)) << 4));
                ldm4(bl, B + r * 128 + (((u + 4) ^ (r & 7)) << 4));
#pragma unroll
                for (int mt = 0; mt < 2; mt++) {
                    mmabf(acc[mt][2 * np],     ah[mt], bh);
                    mmabf(acc[mt][2 * np + 1], ah[mt], bh + 2);
                    mmabf(acc[mt][2 * np],     ah[mt], bl);
                    mmabf(acc[mt][2 * np + 1], ah[mt], bl + 2);
                    mmabf(acc[mt][2 * np],     al[mt], bh);
                    mmabf(acc[mt][2 * np + 1], al[mt], bh + 2);
                }
            }
        }
        __syncthreads();
    }

    // stage accumulators to smem [128][132] floats
    float* sf = reinterpret_cast<float*>(dsm + (sb - dyn));
    const int g = lane >> 2, c2 = (lane & 3) * 2;
#pragma unroll
    for (int mt = 0; mt < 2; mt++)
#pragma unroll
        for (int nt = 0; nt < 8; nt++) {
            int row = wm * 32 + mt * 16 + g;
            int col = wn * 64 + nt * 8 + c2;
            sf[row * 132 + col]           = acc[mt][nt][0];
            sf[row * 132 + col + 1]       = acc[mt][nt][1];
            sf[(row + 8) * 132 + col]     = acc[mt][nt][2];
            sf[(row + 8) * 132 + col + 1] = acc[mt][nt][3];
        }
    __syncthreads();

    if (EPI == 0) {
#pragma unroll
        for (int it = 0; it < 16; it++) {
            int idx = tid + it * 256;          // 0..4095
            int row = idx >> 5, c4 = (idx & 31) << 2;
            const float* spv = sf + row * 132 + c4;
            float4 v;
            v.x = spv[0] + bias[n0 + c4 + 0];
            v.y = spv[1] + bias[n0 + c4 + 1];
            v.z = spv[2] + bias[n0 + c4 + 2];
            v.w = spv[3] + bias[n0 + c4 + 3];
            *reinterpret_cast<float4*>(C + (size_t)(m0 + row) * 512 + n0 + c4) = v;
        }
    } else {
        const int d0 = n0 >> 3;
#pragma unroll
        for (int it = 0; it < 4; it++) {
            int task = tid + it * 256;         // 0..1023
            int row = task >> 3, hh = task & 7;
            int m = m0 + row;
            int bg = m / Ntok, nl = m - bg * Ntok;
            size_t ob = (((size_t)bg * 8 + hh) * Ntok + nl) * 64 + d0;
            const float* spv = sf + row * 132 + hh;
#pragma unroll
            for (int j = 0; j < 16; j++) {
                float v = (spv[j * 8] + bias[((d0 + j) << 3) + hh]) * oscale;
                ushort2 s = split_bf(v);
                Chi[ob + j] = s.x;
                Clo[ob + j] = s.y;
            }
        }
    }
}

// ---------------- LayerNorm fused with hi/lo split ----------------
__global__ void __launch_bounds__(256) layernorm_hilo(const float* __restrict__ in,
                                                      const float* __restrict__ gamma,
                                                      const float* __restrict__ beta,
                                                      ushort2* __restrict__ outhi,
                                                      ushort2* __restrict__ outlo)
{
    int row = blockIdx.x;
    float2 v = reinterpret_cast<const float2*>(in + (size_t)row * 512)[threadIdx.x];
    float s  = v.x + v.y;
    float ss = v.x * v.x + v.y * v.y;
#pragma unroll
    for (int o = 16; o; o >>= 1) {
        s  += __shfl_xor_sync(0xffffffffu, s, o);
        ss += __shfl_xor_sync(0xffffffffu, ss, o);
    }
    __shared__ float rs[8], rss[8];
    int w = threadIdx.x >> 5;
    if ((threadIdx.x & 31) == 0) { rs[w] = s; rss[w] = ss; }
    __syncthreads();
    float ts = 0.f, tss = 0.f;
#pragma unroll
    for (int i = 0; i < 8; i++) { ts += rs[i]; tss += rss[i]; }
    float mean = ts * (1.f / 512.f);
    float var  = tss * (1.f / 512.f) - mean * mean;
    float inv  = rsqrtf(var + 1e-6f);
    int c = threadIdx.x * 2;
    float ox = (v.x - mean) * inv * gamma[c]     + beta[c];
    float oy = (v.y - mean) * inv * gamma[c + 1] + beta[c + 1];
    ushort2 sx = split_bf(ox), sy = split_bf(oy);
    outhi[row * 256 + threadIdx.x] = make_ushort2(sx.x, sy.x);
    outlo[row * 256 + threadIdx.x] = make_ushort2(sx.y, sy.y);
}

// ---------------- tensor-core flash attention (3-term, 2 CTAs/SM) ----------------
// Q is pre-scaled by 1/8 at the projection epilogue.
#define ATTN_SMEM (32768 + 2 * 32768 + 1024)

__global__ void __launch_bounds__(256, 2) attn_mma(
    const u16* __restrict__ Qhi, const u16* __restrict__ Qlo,
    const u16* __restrict__ Khi, const u16* __restrict__ Klo,
    const u16* __restrict__ Vhi, const u16* __restrict__ Vlo,
    u16* __restrict__ AOhi, u16* __restrict__ AOlo)
{
    extern __shared__ char dsm[];
    const int tid = threadIdx.x, lane = tid & 31, wid = tid >> 5;
    const int q0 = blockIdx.x * 128;
    const int h = blockIdx.y, b = blockIdx.z;

    uint32_t dyn = smem_u32(dsm);
    uint32_t sb  = (dyn + 1023) & ~1023u;
    uint32_t Qh_s = sb, Ql_s = sb + 16384;
    uint32_t kvbase = sb + 32768;

    const size_t bh = (size_t)b * 8 + h;
    const u16* qh_g = Qhi + (bh * NTOK + q0) * 64;
    const u16* ql_g = Qlo + (bh * NTOK + q0) * 64;
    const u16* kv_g[4];
    kv_g[0] = Khi + bh * NKV * 64;
    kv_g[1] = Klo + bh * NKV * 64;
    kv_g[2] = Vhi + bh * NKV * 64;
    kv_g[3] = Vlo + bh * NKV * 64;

#pragma unroll
    for (int it = 0; it < 4; it++) {
        int idx = tid + it * 256;
        int r = idx >> 3, u = idx & 7;
        uint32_t off = (uint32_t)(r * 128 + ((u ^ (r & 7)) << 4));
        cp16(Qh_s + off, qh_g + (size_t)r * 64 + u * 8);
        cp16(Ql_s + off, ql_g + (size_t)r * 64 + u * 8);
    }

    auto load_kv = [&](int kt) {
        uint32_t bb = kvbase + (kt & 1) * 32768;
#pragma unroll
        for (int t = 0; t < 4; t++) {
            uint32_t sp = bb + t * 8192;
            const u16* g = kv_g[t] + (size_t)kt * 64 * 64;
#pragma unroll
            for (int it = 0; it < 2; it++) {
                int idx = tid + it * 256;
                int r = idx >> 3, u = idx & 7;
                cp16(sp + r * 128 + ((u ^ (r & 7)) << 4), g + (size_t)r * 64 + u * 8);
            }
        }
        CP_COMMIT();
    };

    load_kv(0);

    const int g = lane >> 2, c2 = (lane & 3) * 2;
    float m0_ = -1e30f, m1_ = -1e30f, l0_ = 0.f, l1_ = 0.f;
    float oacc[8][4];
#pragma unroll
    for (int i = 0; i < 8; i++)
#pragma unroll
        for (int j = 0; j < 4; j++) oacc[i][j] = 0.f;

    for (int kt = 0; kt < 16; kt++) {
        if (kt + 1 < 16) { load_kv(kt + 1); CP_WAIT1(); }
        else             { CP_WAIT0(); }
        __syncthreads();

        uint32_t bb = kvbase + (kt & 1) * 32768;
        uint32_t Kh_s = bb, Kl_s = bb + 8192, Vh_s = bb + 16384, Vl_s = bb + 24576;

        // ---- S = QK^T (3-term; Q pre-scaled) ----
        float sacc[8][4];
#pragma unroll
        for (int i = 0; i < 8; i++)
#pragma unroll
            for (int j = 0; j < 4; j++) sacc[i][j] = 0.f;

#pragma unroll
        for (int ks = 0; ks < 4; ks++) {
            uint32_t qh_f[4], ql_f[4];
            {
                int r = wid * 16 + (lane & 15);
                int u = 2 * ks + (lane >> 4);
                uint32_t off = (uint32_t)(r * 128 + ((u ^ (r & 7)) << 4));
                ldm4(qh_f, Qh_s + off);
                ldm4(ql_f, Ql_s + off);
            }
#pragma unroll
            for (int np = 0; np < 4; np++) {
                uint32_t kh_f[4], kl_f[4];
                int r = np * 16 + ((lane >> 4) << 3) + (lane & 7);
                int u = 2 * ks + ((lane >> 3) & 1);
                uint32_t off = (uint32_t)(r * 128 + ((u ^ (r & 7)) << 4));
                ldm4(kh_f, Kh_s + off);
                ldm4(kl_f, Kl_s + off);
                mmabf(sacc[2 * np],     qh_f, kh_f);
                mmabf(sacc[2 * np + 1], qh_f, kh_f + 2);
                mmabf(sacc[2 * np],     qh_f, kl_f);
                mmabf(sacc[2 * np + 1], qh_f, kl_f + 2);
                mmabf(sacc[2 * np],     ql_f, kh_f);
                mmabf(sacc[2 * np + 1], ql_f, kh_f + 2);
            }
        }

        // ---- online softmax ----
        float mx0 = -1e30f, mx1 = -1e30f;
#pragma unroll
        for (int nt = 0; nt < 8; nt++) {
            mx0 = fmaxf(mx0, fmaxf(sacc[nt][0], sacc[nt][1]));
            mx1 = fmaxf(mx1, fmaxf(sacc[nt][2], sacc[nt][3]));
        }
        mx0 = fmaxf(mx0, __shfl_xor_sync(0xffffffffu, mx0, 1));
        mx0 = fmaxf(mx0, __shfl_xor_sync(0xffffffffu, mx0, 2));
        mx1 = fmaxf(mx1, __shfl_xor_sync(0xffffffffu, mx1, 1));
        mx1 = fmaxf(mx1, __shfl_xor_sync(0xffffffffu, mx1, 2));
        float mn0 = fmaxf(m0_, mx0), mn1 = fmaxf(m1_, mx1);
        float a0 = __expf(m0_ - mn0), a1 = __expf(m1_ - mn1);
        float rs0 = 0.f, rs1 = 0.f;
#pragma unroll
        for (int nt = 0; nt < 8; nt++) {
            sacc[nt][0] = __expf(sacc[nt][0] - mn0);
            sacc[nt][1] = __expf(sacc[nt][1] - mn0);
            sacc[nt][2] = __expf(sacc[nt][2] - mn1);
            sacc[nt][3] = __expf(sacc[nt][3] - mn1);
            rs0 += sacc[nt][0] + sacc[nt][1];
            rs1 += sacc[nt][2] + sacc[nt][3];
        }
        rs0 += __shfl_xor_sync(0xffffffffu, rs0, 1);
        rs0 += __shfl_xor_sync(0xffffffffu, rs0, 2);
        rs1 += __shfl_xor_sync(0xffffffffu, rs1, 1);
        rs1 += __shfl_xor_sync(0xffffffffu, rs1, 2);
        l0_ = l0_ * a0 + rs0;
        l1_ = l1_ * a1 + rs1;
        m0_ = mn0; m1_ = mn1;
#pragma unroll
        for (int dt = 0; dt < 8; dt++) {
            oacc[dt][0] *= a0; oacc[dt][1] *= a0;
            oacc[dt][2] *= a1; oacc[dt][3] *= a1;
        }

        // ---- pack P into A-fragments (hi/lo) ----
        uint32_t ph[4][4], pl[4][4];
#pragma unroll
        for (int j = 0; j < 4; j++) {
            split_pack2(sacc[2 * j][0],     sacc[2 * j][1],     ph[j][0], pl[j][0]);
            split_pack2(sacc[2 * j][2],     sacc[2 * j][3],     ph[j][1], pl[j][1]);
            split_pack2(sacc[2 * j + 1][0], sacc[2 * j + 1][1], ph[j][2], pl[j][2]);
            split_pack2(sacc[2 * j + 1][2], sacc[2 * j + 1][3], ph[j][3], pl[j][3]);
        }

        // ---- O += P V (3-term) ----
#pragma unroll
        for (int j = 0; j < 4; j++) {
#pragma unroll
            for (int dp = 0; dp < 4; dp++) {
                uint32_t vh_f[4], vl_f[4];
                int r = j * 16 + ((lane >> 3) & 1) * 8 + (lane & 7);
                int u = 2 * dp + (lane >> 4);
                uint32_t off = (uint32_t)(r * 128 + ((u ^ (r & 7)) << 4));
                ldm4t(vh_f, Vh_s + off);
                ldm4t(vl_f, Vl_s + off);
                mmabf(oacc[2 * dp],     ph[j], vh_f);
                mmabf(oacc[2 * dp + 1], ph[j], vh_f + 2);
                mmabf(oacc[2 * dp],     ph[j], vl_f);
                mmabf(oacc[2 * dp + 1], ph[j], vl_f + 2);
                mmabf(oacc[2 * dp],     pl[j], vh_f);
                mmabf(oacc[2 * dp + 1], pl[j], vh_f + 2);
            }
        }
        __syncthreads();
    }

    // ---- epilogue ----
    float i0 = 1.f / l0_, i1 = 1.f / l1_;
    int qr0 = q0 + wid * 16 + g;
    size_t base0 = ((size_t)b * NTOK + qr0) * 512 + h * 64;
    size_t base1 = ((size_t)b * NTOK + qr0 + 8) * 512 + h * 64;
#pragma unroll
    for (int dt = 0; dt < 8; dt++) {
        int d = dt * 8 + c2;
        uint32_t rh, rl;
        split_pack2(oacc[dt][0] * i0, oacc[dt][1] * i0, rh, rl);
        *reinterpret_cast<uint32_t*>(AOhi + base0 + d) = rh;
        *reinterpret_cast<uint32_t*>(AOlo + base0 + d) = rl;
        split_pack2(oacc[dt][2] * i1, oacc[dt][3] * i1, rh, rl);
        *reinterpret_cast<uint32_t*>(AOhi + base1 + d) = rh;
        *reinterpret_cast<uint32_t*>(AOlo + base1 + d) = rl;
    }
}

// ---------------- launcher ----------------
extern "C" void kernel_launch(void* const* d_in, const int* in_sizes, int n_in,
                              void* d_out, int out_size)
{
    (void)in_sizes; (void)n_in; (void)out_size;
    const float* x    = (const float*)d_in[0];
    const float* Wq   = (const float*)d_in[1];
    const float* bq   = (const float*)d_in[2];
    const float* Wk   = (const float*)d_in[3];
    const float* bk   = (const float*)d_in[4];
    const float* Wv   = (const float*)d_in[5];
    const float* bv   = (const float*)d_in[6];
    const float* Wp   = (const float*)d_in[7];
    const float* bp   = (const float*)d_in[8];
    const float* sr_w = (const float*)d_in[9];
    const float* sr_b = (const float*)d_in[10];
    const float* ln_g = (const float*)d_in[11];
    const float* ln_b = (const float*)d_in[12];
    float* out = (float*)d_out;

    u16 *xph, *xpl, *xh, *xl, *kvnh, *kvnl, *qhh, *qhl, *khh, *khl, *vhh, *vhl, *aoh, *aol;
    u16 *wqh, *wql, *wkh, *wkl, *wvh, *wvl, *wph, *wpl, *swh, *swl;
    float *kv;
    cudaGetSymbolAddress((void**)&xph,  g_xp_hi);  cudaGetSymbolAddress((void**)&xpl,  g_xp_lo);
    cudaGetSymbolAddress((void**)&xh,   g_x_hi);   cudaGetSymbolAddress((void**)&xl,   g_x_lo);
    cudaGetSymbolAddress((void**)&kvnh, g_kvn_hi); cudaGetSymbolAddress((void**)&kvnl, g_kvn_lo);
    cudaGetSymbolAddress((void**)&qhh,  g_q_hi);   cudaGetSymbolAddress((void**)&qhl,  g_q_lo);
    cudaGetSymbolAddress((void**)&khh,  g_k_hi);   cudaGetSymbolAddress((void**)&khl,  g_k_lo);
    cudaGetSymbolAddress((void**)&vhh,  g_v_hi);   cudaGetSymbolAddress((void**)&vhl,  g_v_lo);
    cudaGetSymbolAddress((void**)&aoh,  g_ao_hi);  cudaGetSymbolAddress((void**)&aol,  g_ao_lo);
    cudaGetSymbolAddress((void**)&wqh,  g_wq_hi);  cudaGetSymbolAddress((void**)&wql,  g_wq_lo);
    cudaGetSymbolAddress((void**)&wkh,  g_wk_hi);  cudaGetSymbolAddress((void**)&wkl,  g_wk_lo);
    cudaGetSymbolAddress((void**)&wvh,  g_wv_hi);  cudaGetSymbolAddress((void**)&wvl,  g_wv_lo);
    cudaGetSymbolAddress((void**)&wph,  g_wp_hi);  cudaGetSymbolAddress((void**)&wpl,  g_wp_lo);
    cudaGetSymbolAddress((void**)&swh,  g_sw_hi);  cudaGetSymbolAddress((void**)&swl,  g_sw_lo);
    cudaGetSymbolAddress((void**)&kv,   g_kv);

    cudaFuncSetAttribute(gemm_mma<0>, cudaFuncAttributeMaxDynamicSharedMemorySize, GSMEM);
    cudaFuncSetAttribute(gemm_mma<1>, cudaFuncAttributeMaxDynamicSharedMemorySize, GSMEM);
    cudaFuncSetAttribute(attn_mma, cudaFuncAttributeMaxDynamicSharedMemorySize, ATTN_SMEM);

    // 1-4: conversions (ordered so launch #6 = Q-projection GEMM for ncu -s 5 -c 1)
    im2col_hilo<<<8192, 256>>>(x, (ushort4*)xph, (ushort4*)xpl);
    cvt_hilo<<<8192, 256>>>((const float4*)x, (ushort4*)xh, (ushort4*)xl, 2097152);
    wT_hilo<<<dim3(16, 64), dim3(32, 8)>>>(sr_w, swh, swl, 2048, 512);
    wT4_hilo<<<dim3(16, 16, 4), dim3(32, 8)>>>(Wq, Wk, Wv, Wp,
                                               wqh, wql, wkh, wkl, wvh, wvl, wph, wpl);

    // 5: conv GEMM [4096,2048]x[2048,512] + sr_b -> fp32 kv
    gemm_mma<0><<<dim3(4, 32), 256, GSMEM>>>(xph, xpl, swh, swl, sr_b, 1.f, kv, 0, 0, 2048, 0);
    // 6: Q projection (scaled by 1/8) -> head-major bf16 hi/lo   [PROFILED]
    gemm_mma<1><<<dim3(4, 128), 256, GSMEM>>>(xh, xl, wqh, wql, bq, 0.125f, 0, qhh, qhl, 512, 4096);
    // 7: LayerNorm -> bf16 hi/lo
    layernorm_hilo<<<4096, 256>>>(kv, ln_g, ln_b, (ushort2*)kvnh, (ushort2*)kvnl);
    // 8-9: K / V projections -> head-major bf16 hi/lo
    gemm_mma<1><<<dim3(4, 32), 256, GSMEM>>>(kvnh, kvnl, wkh, wkl, bk, 1.f, 0, khh, khl, 512, 1024);
    gemm_mma<1><<<dim3(4, 32), 256, GSMEM>>>(kvnh, kvnl, wvh, wvl, bv, 1.f, 0, vhh, vhl, 512, 1024);
    // 10: attention -> bf16 hi/lo concat layout
    attn_mma<<<dim3(32, 8, 4), 256, ATTN_SMEM>>>(qhh, qhl, khh, khl, vhh, vhl, aoh, aol);
    // 11: output projection -> d_out
    gemm_mma<0><<<dim3(4, 128), 256, GSMEM>>>(aoh, aol, wph, wpl, bp, 1.f, out, 0, 0, 512, 0);
}

// round 9
// speedup vs baseline: 1.4813x; 1.4813x over previous
#include <cuda_runtime.h>
#include <cuda_bf16.h>
#include <math.h>
#include <stdint.h>

// ---------------- problem constants ----------------
#define NTOK 4096
#define NKV  1024

typedef unsigned short u16;

// ---------------- low-level helpers (compute_103-baseline PTX only) ----------------
__device__ __forceinline__ uint32_t smem_u32(const void* p) {
    uint32_t a;
    asm("{ .reg .u64 t; cvta.to.shared.u64 t, %1; cvt.u32.u64 %0, t; }" : "=r"(a) : "l"(p));
    return a;
}
__device__ __forceinline__ void cp16(uint32_t s, const void* g) {
    asm volatile("cp.async.cg.shared.global [%0], [%1], 16;" :: "r"(s), "l"(g));
}
#define CP_COMMIT() asm volatile("cp.async.commit_group;" ::: "memory")
#define CP_WAIT0()  asm volatile("cp.async.wait_group 0;" ::: "memory")
#define CP_WAIT1()  asm volatile("cp.async.wait_group 1;" ::: "memory")

__device__ __forceinline__ void ldm4(uint32_t* r, uint32_t a) {
    asm volatile("ldmatrix.sync.aligned.m8n8.x4.shared.b16 {%0,%1,%2,%3}, [%4];"
                 : "=r"(r[0]), "=r"(r[1]), "=r"(r[2]), "=r"(r[3]) : "r"(a));
}
__device__ __forceinline__ void ldm4t(uint32_t* r, uint32_t a) {
    asm volatile("ldmatrix.sync.aligned.m8n8.x4.trans.shared.b16 {%0,%1,%2,%3}, [%4];"
                 : "=r"(r[0]), "=r"(r[1]), "=r"(r[2]), "=r"(r[3]) : "r"(a));
}
__device__ __forceinline__ void mmabf(float* d, const uint32_t* a, const uint32_t* b) {
    asm volatile("mma.sync.aligned.m16n8k16.row.col.f32.bf16.bf16.f32 "
                 "{%0,%1,%2,%3}, {%4,%5,%6,%7}, {%8,%9}, {%0,%1,%2,%3};"
                 : "+f"(d[0]), "+f"(d[1]), "+f"(d[2]), "+f"(d[3])
                 : "r"(a[0]), "r"(a[1]), "r"(a[2]), "r"(a[3]), "r"(b[0]), "r"(b[1]));
}

__device__ __forceinline__ ushort2 split_bf(float x) {
    __nv_bfloat16 h = __float2bfloat16(x);
    __nv_bfloat16 l = __float2bfloat16(x - __bfloat162float(h));
    return make_ushort2(__bfloat16_as_ushort(h), __bfloat16_as_ushort(l));
}
__device__ __forceinline__ void split_pack2(float a, float b, uint32_t& rh, uint32_t& rl) {
    __nv_bfloat16 ah = __float2bfloat16(a), bh = __float2bfloat16(b);
    __nv_bfloat16 al = __float2bfloat16(a - __bfloat162float(ah));
    __nv_bfloat16 bl = __float2bfloat16(b - __bfloat162float(bh));
    rh = (uint32_t)__bfloat16_as_ushort(ah) | ((uint32_t)__bfloat16_as_ushort(bh) << 16);
    rl = (uint32_t)__bfloat16_as_ushort(al) | ((uint32_t)__bfloat16_as_ushort(bl) << 16);
}

// ---------------- device scratch ----------------
__device__ u16 g_xp_hi [4096u * 2048u], g_xp_lo [4096u * 2048u];
__device__ u16 g_x_hi  [16384u * 512u], g_x_lo  [16384u * 512u];
__device__ u16 g_kvn_hi[4096u * 512u],  g_kvn_lo[4096u * 512u];
__device__ u16 g_q_hi  [16384u * 512u], g_q_lo  [16384u * 512u];
__device__ u16 g_k_hi  [4096u * 512u],  g_k_lo  [4096u * 512u];
__device__ u16 g_v_hi  [4096u * 512u],  g_v_lo  [4096u * 512u];
__device__ u16 g_ao_hi [16384u * 512u], g_ao_lo [16384u * 512u];
__device__ u16 g_wq_hi [512u * 512u],   g_wq_lo [512u * 512u];
__device__ u16 g_wk_hi [512u * 512u],   g_wk_lo [512u * 512u];
__device__ u16 g_wv_hi [512u * 512u],   g_wv_lo [512u * 512u];
__device__ u16 g_wp_hi [512u * 512u],   g_wp_lo [512u * 512u];
__device__ u16 g_sw_hi [512u * 2048u],  g_sw_lo [512u * 2048u];
__device__ float g_kv[4096u * 512u];

// ---------------- im2col (2x2 stride-2) fused with hi/lo split ----------------
__global__ void __launch_bounds__(256) im2col_hilo(const float* __restrict__ x,
                                                   ushort4* __restrict__ hi,
                                                   ushort4* __restrict__ lo)
{
    int id  = blockIdx.x * blockDim.x + threadIdx.x;   // float4 index, 2097152 total
    int row = id >> 9;
    int k   = (id & 511) * 4;
    int p   = k >> 9, c = k & 511;
    int di  = p >> 1, dj = p & 1;
    int b   = row >> 10, rem = row & 1023;
    int i   = rem >> 5,  j   = rem & 31;
    int srow = b * 4096 + (2 * i + di) * 64 + (2 * j + dj);
    float4 v = reinterpret_cast<const float4*>(x)[(size_t)(srow * 512 + c) >> 2];
    ushort2 a = split_bf(v.x), bb = split_bf(v.y), cc = split_bf(v.z), d = split_bf(v.w);
    hi[id] = make_ushort4(a.x, bb.x, cc.x, d.x);
    lo[id] = make_ushort4(a.y, bb.y, cc.y, d.y);
}

// ---------------- generic fp32 -> hi/lo ----------------
__global__ void __launch_bounds__(256) cvt_hilo(const float4* __restrict__ src,
                                                ushort4* __restrict__ hi,
                                                ushort4* __restrict__ lo, int n4)
{
    int id = blockIdx.x * blockDim.x + threadIdx.x;
    if (id >= n4) return;
    float4 v = src[id];
    ushort2 a = split_bf(v.x), b = split_bf(v.y), c = split_bf(v.z), d = split_bf(v.w);
    hi[id] = make_ushort4(a.x, b.x, c.x, d.x);
    lo[id] = make_ushort4(a.y, b.y, c.y, d.y);
}

// ---------------- weight transpose + hi/lo split: W[K,N] -> T[N,K] ----------------
__global__ void wT_hilo(const float* __restrict__ W,
                        u16* __restrict__ Thi, u16* __restrict__ Tlo, int K, int N)
{
    __shared__ float t[32][33];
    int n0 = blockIdx.x * 32, k0 = blockIdx.y * 32;
    for (int i = threadIdx.y; i < 32; i += 8)
        t[i][threadIdx.x] = W[(size_t)(k0 + i) * N + n0 + threadIdx.x];
    __syncthreads();
    for (int i = threadIdx.y; i < 32; i += 8) {
        ushort2 s = split_bf(t[threadIdx.x][i]);
        size_t o = (size_t)(n0 + i) * K + k0 + threadIdx.x;
        Thi[o] = s.x; Tlo[o] = s.y;
    }
}

// 4 x (512x512) weight transposes in one launch; blockIdx.z selects the tensor.
__global__ void wT4_hilo(const float* __restrict__ W0, const float* __restrict__ W1,
                         const float* __restrict__ W2, const float* __restrict__ W3,
                         u16* __restrict__ H0, u16* __restrict__ L0,
                         u16* __restrict__ H1, u16* __restrict__ L1,
                         u16* __restrict__ H2, u16* __restrict__ L2,
                         u16* __restrict__ H3, u16* __restrict__ L3)
{
    const float* W; u16 *Thi, *Tlo;
    switch (blockIdx.z) {
        case 0:  W = W0; Thi = H0; Tlo = L0; break;
        case 1:  W = W1; Thi = H1; Tlo = L1; break;
        case 2:  W = W2; Thi = H2; Tlo = L2; break;
        default: W = W3; Thi = H3; Tlo = L3; break;
    }
    __shared__ float t[32][33];
    int n0 = blockIdx.x * 32, k0 = blockIdx.y * 32;
    for (int i = threadIdx.y; i < 32; i += 8)
        t[i][threadIdx.x] = W[(size_t)(k0 + i) * 512 + n0 + threadIdx.x];
    __syncthreads();
    for (int i = threadIdx.y; i < 32; i += 8) {
        ushort2 s = split_bf(t[threadIdx.x][i]);
        size_t o = (size_t)(n0 + i) * 512 + k0 + threadIdx.x;
        Thi[o] = s.x; Tlo[o] = s.y;
    }
}

// ---------------- mma.sync bf16 3-term GEMM, 128x64 tile, BK=64, 2 CTAs/SM ----------------
// C[m,n] = sum_k A[m,k] * B[n,k] + bias[n]  (A: [M,K] hi/lo, B: [N,K] hi/lo)
// EPI==0: fp32 row-major C [M,512]
// EPI==1: head-major hi/lo scatter: n -> (h=n%8, d=n/8), output scaled by oscale
#define GSMEM (2 * 49152 + 1024)

template <int EPI>
__global__ void __launch_bounds__(256, 2) gemm_mma(
    const u16* __restrict__ Ahi, const u16* __restrict__ Alo,
    const u16* __restrict__ Bhi, const u16* __restrict__ Blo,
    const float* __restrict__ bias, float oscale, float* __restrict__ C,
    u16* __restrict__ Chi, u16* __restrict__ Clo, int K, int Ntok)
{
    extern __shared__ char dsm[];
    const int tid = threadIdx.x, lane = tid & 31, wid = tid >> 5;
    const int wm = wid & 3, wn = wid >> 2;
    const int m0 = blockIdx.y * 128, n0 = blockIdx.x * 64;

    uint32_t dyn = smem_u32(dsm);
    uint32_t sb  = (dyn + 1023) & ~1023u;

    const u16* sA0 = Ahi + (size_t)m0 * K;
    const u16* sA1 = Alo + (size_t)m0 * K;
    const u16* sB0 = Bhi + (size_t)n0 * K;
    const u16* sB1 = Blo + (size_t)n0 * K;

    float acc[2][4][4];
#pragma unroll
    for (int a = 0; a < 2; a++)
#pragma unroll
        for (int b = 0; b < 4; b++)
#pragma unroll
            for (int c = 0; c < 4; c++) acc[a][b][c] = 0.f;

    const int NC = K >> 6;

    auto load_chunk = [&](int i) {
        int buf = i & 1, kk0 = i << 6;
        uint32_t bb = sb + buf * 49152;
#pragma unroll
        for (int it = 0; it < 4; it++) {
            int idx = tid + it * 256;
            int r = idx >> 3, u = idx & 7;
            uint32_t off = (uint32_t)(r * 128 + ((u ^ (r & 7)) << 4));
            cp16(bb + off,         sA0 + (size_t)r * K + kk0 + u * 8);
            cp16(bb + 16384 + off, sA1 + (size_t)r * K + kk0 + u * 8);
        }
#pragma unroll
        for (int it = 0; it < 2; it++) {
            int idx = tid + it * 256;
            int r = idx >> 3, u = idx & 7;
            uint32_t off = (uint32_t)(r * 128 + ((u ^ (r & 7)) << 4));
            cp16(bb + 32768 + off, sB0 + (size_t)r * K + kk0 + u * 8);
            cp16(bb + 40960 + off, sB1 + (size_t)r * K + kk0 + u * 8);
        }
        CP_COMMIT();
    };

    load_chunk(0);
    for (int i = 0; i < NC; i++) {
        if (i + 1 < NC) { load_chunk(i + 1); CP_WAIT1(); }
        else            { CP_WAIT0(); }
        __syncthreads();

        uint32_t base = sb + (i & 1) * 49152;
        uint32_t Ah = base, Al = base + 16384, Bh = base + 32768, Bl = base + 40960;
#pragma unroll
        for (int ks = 0; ks < 4; ks++) {
            uint32_t ah[2][4], al[2][4];
#pragma unroll
            for (int mt = 0; mt < 2; mt++) {
                int r = wm * 32 + mt * 16 + (lane & 15);
                int u = 2 * ks + (lane >> 4);
                uint32_t off = (uint32_t)(r * 128 + ((u ^ (r & 7)) << 4));
                ldm4(ah[mt], Ah + off);
                ldm4(al[mt], Al + off);
            }
#pragma unroll
            for (int np = 0; np < 2; np++) {
                uint32_t bh[4], bl[4];
                int r = wn * 32 + np * 16 + ((lane >> 4) << 3) + (lane & 7);
                int u = 2 * ks + ((lane >> 3) & 1);
                uint32_t off = (uint32_t)(r * 128 + ((u ^ (r & 7)) << 4));
                ldm4(bh, Bh + off);
                ldm4(bl, Bl + off);
#pragma unroll
                for (int mt = 0; mt < 2; mt++) {
                    mmabf(acc[mt][2 * np],     ah[mt], bh);
                    mmabf(acc[mt][2 * np + 1], ah[mt], bh + 2);
                    mmabf(acc[mt][2 * np],     ah[mt], bl);
                    mmabf(acc[mt][2 * np + 1], ah[mt], bl + 2);
                    mmabf(acc[mt][2 * np],     al[mt], bh);
                    mmabf(acc[mt][2 * np + 1], al[mt], bh + 2);
                }
            }
        }
        __syncthreads();
    }

    // stage accumulators to smem [128][68] floats
    float* sf = reinterpret_cast<float*>(dsm + (sb - dyn));
    const int g = lane >> 2, c2 = (lane & 3) * 2;
#pragma unroll
    for (int mt = 0; mt < 2; mt++)
#pragma unroll
        for (int nt = 0; nt < 4; nt++) {
            int row = wm * 32 + mt * 16 + g;
            int col = wn * 32 + nt * 8 + c2;
            sf[row * 68 + col]           = acc[mt][nt][0];
            sf[row * 68 + col + 1]       = acc[mt][nt][1];
            sf[(row + 8) * 68 + col]     = acc[mt][nt][2];
            sf[(row + 8) * 68 + col + 1] = acc[mt][nt][3];
        }
    __syncthreads();

    if (EPI == 0) {
#pragma unroll
        for (int it = 0; it < 8; it++) {
            int idx = tid + it * 256;          // 0..2047
            int row = idx >> 4, c4 = (idx & 15) << 2;
            const float* spv = sf + row * 68 + c4;
            float4 v;
            v.x = spv[0] + bias[n0 + c4 + 0];
            v.y = spv[1] + bias[n0 + c4 + 1];
            v.z = spv[2] + bias[n0 + c4 + 2];
            v.w = spv[3] + bias[n0 + c4 + 3];
            *reinterpret_cast<float4*>(C + (size_t)(m0 + row) * 512 + n0 + c4) = v;
        }
    } else {
        const int d0 = n0 >> 3;
#pragma unroll
        for (int it = 0; it < 4; it++) {
            int task = tid + it * 256;         // 0..1023
            int row = task >> 3, hh = task & 7;
            int m = m0 + row;
            int bg = m / Ntok, nl = m - bg * Ntok;
            size_t ob = (((size_t)bg * 8 + hh) * Ntok + nl) * 64 + d0;  // 8-elt aligned
            const float* spv = sf + row * 68 + hh;
            u16 hbuf[8], lbuf[8];
#pragma unroll
            for (int j = 0; j < 8; j++) {
                float v = (spv[j * 8] + bias[n0 + (j << 3) + hh]) * oscale;
                ushort2 s = split_bf(v);
                hbuf[j] = s.x;
                lbuf[j] = s.y;
            }
            *reinterpret_cast<uint4*>(Chi + ob) = *reinterpret_cast<const uint4*>(hbuf);
            *reinterpret_cast<uint4*>(Clo + ob) = *reinterpret_cast<const uint4*>(lbuf);
        }
    }
}

// ---------------- LayerNorm fused with hi/lo split ----------------
__global__ void __launch_bounds__(256) layernorm_hilo(const float* __restrict__ in,
                                                      const float* __restrict__ gamma,
                                                      const float* __restrict__ beta,
                                                      ushort2* __restrict__ outhi,
                                                      ushort2* __restrict__ outlo)
{
    int row = blockIdx.x;
    float2 v = reinterpret_cast<const float2*>(in + (size_t)row * 512)[threadIdx.x];
    float s  = v.x + v.y;
    float ss = v.x * v.x + v.y * v.y;
#pragma unroll
    for (int o = 16; o; o >>= 1) {
        s  += __shfl_xor_sync(0xffffffffu, s, o);
        ss += __shfl_xor_sync(0xffffffffu, ss, o);
    }
    __shared__ float rs[8], rss[8];
    int w = threadIdx.x >> 5;
    if ((threadIdx.x & 31) == 0) { rs[w] = s; rss[w] = ss; }
    __syncthreads();
    float ts = 0.f, tss = 0.f;
#pragma unroll
    for (int i = 0; i < 8; i++) { ts += rs[i]; tss += rss[i]; }
    float mean = ts * (1.f / 512.f);
    float var  = tss * (1.f / 512.f) - mean * mean;
    float inv  = rsqrtf(var + 1e-6f);
    int c = threadIdx.x * 2;
    float ox = (v.x - mean) * inv * gamma[c]     + beta[c];
    float oy = (v.y - mean) * inv * gamma[c + 1] + beta[c + 1];
    ushort2 sx = split_bf(ox), sy = split_bf(oy);
    outhi[row * 256 + threadIdx.x] = make_ushort2(sx.x, sy.x);
    outlo[row * 256 + threadIdx.x] = make_ushort2(sx.y, sy.y);
}

// ---------------- tensor-core flash attention (3-term, 2 CTAs/SM) ----------------
// Q is pre-scaled by 1/8 at the projection epilogue.
#define ATTN_SMEM (32768 + 2 * 32768 + 1024)

__global__ void __launch_bounds__(256, 2) attn_mma(
    const u16* __restrict__ Qhi, const u16* __restrict__ Qlo,
    const u16* __restrict__ Khi, const u16* __restrict__ Klo,
    const u16* __restrict__ Vhi, const u16* __restrict__ Vlo,
    u16* __restrict__ AOhi, u16* __restrict__ AOlo)
{
    extern __shared__ char dsm[];
    const int tid = threadIdx.x, lane = tid & 31, wid = tid >> 5;
    const int q0 = blockIdx.x * 128;
    const int h = blockIdx.y, b = blockIdx.z;

    uint32_t dyn = smem_u32(dsm);
    uint32_t sb  = (dyn + 1023) & ~1023u;
    uint32_t Qh_s = sb, Ql_s = sb + 16384;
    uint32_t kvbase = sb + 32768;

    const size_t bh = (size_t)b * 8 + h;
    const u16* qh_g = Qhi + (bh * NTOK + q0) * 64;
    const u16* ql_g = Qlo + (bh * NTOK + q0) * 64;
    const u16* kv_g[4];
    kv_g[0] = Khi + bh * NKV * 64;
    kv_g[1] = Klo + bh * NKV * 64;
    kv_g[2] = Vhi + bh * NKV * 64;
    kv_g[3] = Vlo + bh * NKV * 64;

#pragma unroll
    for (int it = 0; it < 4; it++) {
        int idx = tid + it * 256;
        int r = idx >> 3, u = idx & 7;
        uint32_t off = (uint32_t)(r * 128 + ((u ^ (r & 7)) << 4));
        cp16(Qh_s + off, qh_g + (size_t)r * 64 + u * 8);
        cp16(Ql_s + off, ql_g + (size_t)r * 64 + u * 8);
    }

    auto load_kv = [&](int kt) {
        uint32_t bb = kvbase + (kt & 1) * 32768;
#pragma unroll
        for (int t = 0; t < 4; t++) {
            uint32_t sp = bb + t * 8192;
            const u16* g = kv_g[t] + (size_t)kt * 64 * 64;
#pragma unroll
            for (int it = 0; it < 2; it++) {
                int idx = tid + it * 256;
                int r = idx >> 3, u = idx & 7;
                cp16(sp + r * 128 + ((u ^ (r & 7)) << 4), g + (size_t)r * 64 + u * 8);
            }
        }
        CP_COMMIT();
    };

    load_kv(0);

    const int g = lane >> 2, c2 = (lane & 3) * 2;
    float m0_ = -1e30f, m1_ = -1e30f, l0_ = 0.f, l1_ = 0.f;
    float oacc[8][4];
#pragma unroll
    for (int i = 0; i < 8; i++)
#pragma unroll
        for (int j = 0; j < 4; j++) oacc[i][j] = 0.f;

    for (int kt = 0; kt < 16; kt++) {
        if (kt + 1 < 16) { load_kv(kt + 1); CP_WAIT1(); }
        else             { CP_WAIT0(); }
        __syncthreads();

        uint32_t bb = kvbase + (kt & 1) * 32768;
        uint32_t Kh_s = bb, Kl_s = bb + 8192, Vh_s = bb + 16384, Vl_s = bb + 24576;

        // ---- S = QK^T (3-term; Q pre-scaled by 1/8) ----
        float sacc[8][4];
#pragma unroll
        for (int i = 0; i < 8; i++)
#pragma unroll
            for (int j = 0; j < 4; j++) sacc[i][j] = 0.f;

#pragma unroll
        for (int ks = 0; ks < 4; ks++) {
            uint32_t qh_f[4], ql_f[4];
            {
                int r = wid * 16 + (lane & 15);
                int u = 2 * ks + (lane >> 4);
                uint32_t off = (uint32_t)(r * 128 + ((u ^ (r & 7)) << 4));
                ldm4(qh_f, Qh_s + off);
                ldm4(ql_f, Ql_s + off);
            }
#pragma unroll
            for (int np = 0; np < 4; np++) {
                uint32_t kh_f[4], kl_f[4];
                int r = np * 16 + ((lane >> 4) << 3) + (lane & 7);
                int u = 2 * ks + ((lane >> 3) & 1);
                uint32_t off = (uint32_t)(r * 128 + ((u ^ (r & 7)) << 4));
                ldm4(kh_f, Kh_s + off);
                ldm4(kl_f, Kl_s + off);
                mmabf(sacc[2 * np],     qh_f, kh_f);
                mmabf(sacc[2 * np + 1], qh_f, kh_f + 2);
                mmabf(sacc[2 * np],     qh_f, kl_f);
                mmabf(sacc[2 * np + 1], qh_f, kl_f + 2);
                mmabf(sacc[2 * np],     ql_f, kh_f);
                mmabf(sacc[2 * np + 1], ql_f, kh_f + 2);
            }
        }

        // ---- online softmax ----
        float mx0 = -1e30f, mx1 = -1e30f;
#pragma unroll
        for (int nt = 0; nt < 8; nt++) {
            mx0 = fmaxf(mx0, fmaxf(sacc[nt][0], sacc[nt][1]));
            mx1 = fmaxf(mx1, fmaxf(sacc[nt][2], sacc[nt][3]));
        }
        mx0 = fmaxf(mx0, __shfl_xor_sync(0xffffffffu, mx0, 1));
        mx0 = fmaxf(mx0, __shfl_xor_sync(0xffffffffu, mx0, 2));
        mx1 = fmaxf(mx1, __shfl_xor_sync(0xffffffffu, mx1, 1));
        mx1 = fmaxf(mx1, __shfl_xor_sync(0xffffffffu, mx1, 2));
        float mn0 = fmaxf(m0_, mx0), mn1 = fmaxf(m1_, mx1);
        float a0 = __expf(m0_ - mn0), a1 = __expf(m1_ - mn1);
        float rs0 = 0.f, rs1 = 0.f;
#pragma unroll
        for (int nt = 0; nt < 8; nt++) {
            sacc[nt][0] = __expf(sacc[nt][0] - mn0);
            sacc[nt][1] = __expf(sacc[nt][1] - mn0);
            sacc[nt][2] = __expf(sacc[nt][2] - mn1);
            sacc[nt][3] = __expf(sacc[nt][3] - mn1);
            rs0 += sacc[nt][0] + sacc[nt][1];
            rs1 += sacc[nt][2] + sacc[nt][3];
        }
        rs0 += __shfl_xor_sync(0xffffffffu, rs0, 1);
        rs0 += __shfl_xor_sync(0xffffffffu, rs0, 2);
        rs1 += __shfl_xor_sync(0xffffffffu, rs1, 1);
        rs1 += __shfl_xor_sync(0xffffffffu, rs1, 2);
        l0_ = l0_ * a0 + rs0;
        l1_ = l1_ * a1 + rs1;
        m0_ = mn0; m1_ = mn1;
#pragma unroll
        for (int dt = 0; dt < 8; dt++) {
            oacc[dt][0] *= a0; oacc[dt][1] *= a0;
            oacc[dt][2] *= a1; oacc[dt][3] *= a1;
        }

        // ---- pack P into A-fragments (hi/lo) ----
        uint32_t ph[4][4], pl[4][4];
#pragma unroll
        for (int j = 0; j < 4; j++) {
            split_pack2(sacc[2 * j][0],     sacc[2 * j][1],     ph[j][0], pl[j][0]);
            split_pack2(sacc[2 * j][2],     sacc[2 * j][3],     ph[j][1], pl[j][1]);
            split_pack2(sacc[2 * j + 1][0], sacc[2 * j + 1][1], ph[j][2], pl[j][2]);
            split_pack2(sacc[2 * j + 1][2], sacc[2 * j + 1][3], ph[j][3], pl[j][3]);
        }

        // ---- O += P V (3-term) ----
#pragma unroll
        for (int j = 0; j < 4; j++) {
#pragma unroll
            for (int dp = 0; dp < 4; dp++) {
                uint32_t vh_f[4], vl_f[4];
                int r = j * 16 + ((lane >> 3) & 1) * 8 + (lane & 7);
                int u = 2 * dp + (lane >> 4);
                uint32_t off = (uint32_t)(r * 128 + ((u ^ (r & 7)) << 4));
                ldm4t(vh_f, Vh_s + off);
                ldm4t(vl_f, Vl_s + off);
                mmabf(oacc[2 * dp],     ph[j], vh_f);
                mmabf(oacc[2 * dp + 1], ph[j], vh_f + 2);
                mmabf(oacc[2 * dp],     ph[j], vl_f);
                mmabf(oacc[2 * dp + 1], ph[j], vl_f + 2);
                mmabf(oacc[2 * dp],     pl[j], vh_f);
                mmabf(oacc[2 * dp + 1], pl[j], vh_f + 2);
            }
        }
        __syncthreads();
    }

    // ---- epilogue ----
    float i0 = 1.f / l0_, i1 = 1.f / l1_;
    int qr0 = q0 + wid * 16 + g;
    size_t base0 = ((size_t)b * NTOK + qr0) * 512 + h * 64;
    size_t base1 = ((size_t)b * NTOK + qr0 + 8) * 512 + h * 64;
#pragma unroll
    for (int dt = 0; dt < 8; dt++) {
        int d = dt * 8 + c2;
        uint32_t rh, rl;
        split_pack2(oacc[dt][0] * i0, oacc[dt][1] * i0, rh, rl);
        *reinterpret_cast<uint32_t*>(AOhi + base0 + d) = rh;
        *reinterpret_cast<uint32_t*>(AOlo + base0 + d) = rl;
        split_pack2(oacc[dt][2] * i1, oacc[dt][3] * i1, rh, rl);
        *reinterpret_cast<uint32_t*>(AOhi + base1 + d) = rh;
        *reinterpret_cast<uint32_t*>(AOlo + base1 + d) = rl;
    }
}

// ---------------- launcher ----------------
extern "C" void kernel_launch(void* const* d_in, const int* in_sizes, int n_in,
                              void* d_out, int out_size)
{
    (void)in_sizes; (void)n_in; (void)out_size;
    const float* x    = (const float*)d_in[0];
    const float* Wq   = (const float*)d_in[1];
    const float* bq   = (const float*)d_in[2];
    const float* Wk   = (const float*)d_in[3];
    const float* bk   = (const float*)d_in[4];
    const float* Wv   = (const float*)d_in[5];
    const float* bv   = (const float*)d_in[6];
    const float* Wp   = (const float*)d_in[7];
    const float* bp   = (const float*)d_in[8];
    const float* sr_w = (const float*)d_in[9];
    const float* sr_b = (const float*)d_in[10];
    const float* ln_g = (const float*)d_in[11];
    const float* ln_b = (const float*)d_in[12];
    float* out = (float*)d_out;

    u16 *xph, *xpl, *xh, *xl, *kvnh, *kvnl, *qhh, *qhl, *khh, *khl, *vhh, *vhl, *aoh, *aol;
    u16 *wqh, *wql, *wkh, *wkl, *wvh, *wvl, *wph, *wpl, *swh, *swl;
    float *kv;
    cudaGetSymbolAddress((void**)&xph,  g_xp_hi);  cudaGetSymbolAddress((void**)&xpl,  g_xp_lo);
    cudaGetSymbolAddress((void**)&xh,   g_x_hi);   cudaGetSymbolAddress((void**)&xl,   g_x_lo);
    cudaGetSymbolAddress((void**)&kvnh, g_kvn_hi); cudaGetSymbolAddress((void**)&kvnl, g_kvn_lo);
    cudaGetSymbolAddress((void**)&qhh,  g_q_hi);   cudaGetSymbolAddress((void**)&qhl,  g_q_lo);
    cudaGetSymbolAddress((void**)&khh,  g_k_hi);   cudaGetSymbolAddress((void**)&khl,  g_k_lo);
    cudaGetSymbolAddress((void**)&vhh,  g_v_hi);   cudaGetSymbolAddress((void**)&vhl,  g_v_lo);
    cudaGetSymbolAddress((void**)&aoh,  g_ao_hi);  cudaGetSymbolAddress((void**)&aol,  g_ao_lo);
    cudaGetSymbolAddress((void**)&wqh,  g_wq_hi);  cudaGetSymbolAddress((void**)&wql,  g_wq_lo);
    cudaGetSymbolAddress((void**)&wkh,  g_wk_hi);  cudaGetSymbolAddress((void**)&wkl,  g_wk_lo);
    cudaGetSymbolAddress((void**)&wvh,  g_wv_hi);  cudaGetSymbolAddress((void**)&wvl,  g_wv_lo);
    cudaGetSymbolAddress((void**)&wph,  g_wp_hi);  cudaGetSymbolAddress((void**)&wpl,  g_wp_lo);
    cudaGetSymbolAddress((void**)&swh,  g_sw_hi);  cudaGetSymbolAddress((void**)&swl,  g_sw_lo);
    cudaGetSymbolAddress((void**)&kv,   g_kv);

    cudaFuncSetAttribute(gemm_mma<0>, cudaFuncAttributeMaxDynamicSharedMemorySize, GSMEM);
    cudaFuncSetAttribute(gemm_mma<1>, cudaFuncAttributeMaxDynamicSharedMemorySize, GSMEM);
    cudaFuncSetAttribute(attn_mma, cudaFuncAttributeMaxDynamicSharedMemorySize, ATTN_SMEM);

    // 1-4: conversions
    im2col_hilo<<<8192, 256>>>(x, (ushort4*)xph, (ushort4*)xpl);
    cvt_hilo<<<8192, 256>>>((const float4*)x, (ushort4*)xh, (ushort4*)xl, 2097152);
    wT_hilo<<<dim3(16, 64), dim3(32, 8)>>>(sr_w, swh, swl, 2048, 512);
    wT4_hilo<<<dim3(16, 16, 4), dim3(32, 8)>>>(Wq, Wk, Wv, Wp,
                                               wqh, wql, wkh, wkl, wvh, wvl, wph, wpl);

    // 5: conv GEMM [4096,2048]x[2048,512] + sr_b -> fp32 kv
    gemm_mma<0><<<dim3(8, 32), 256, GSMEM>>>(xph, xpl, swh, swl, sr_b, 1.f, kv, 0, 0, 2048, 0);
    // 6: Q projection (scaled by 1/8) -> head-major bf16 hi/lo
    gemm_mma<1><<<dim3(8, 128), 256, GSMEM>>>(xh, xl, wqh, wql, bq, 0.125f, 0, qhh, qhl, 512, 4096);
    // 7: LayerNorm -> bf16 hi/lo
    layernorm_hilo<<<4096, 256>>>(kv, ln_g, ln_b, (ushort2*)kvnh, (ushort2*)kvnl);
    // 8-9: K / V projections -> head-major bf16 hi/lo
    gemm_mma<1><<<dim3(8, 32), 256, GSMEM>>>(kvnh, kvnl, wkh, wkl, bk, 1.f, 0, khh, khl, 512, 1024);
    gemm_mma<1><<<dim3(8, 32), 256, GSMEM>>>(kvnh, kvnl, wvh, wvl, bv, 1.f, 0, vhh, vhl, 512, 1024);
    // 10: attention -> bf16 hi/lo concat layout
    attn_mma<<<dim3(32, 8, 4), 256, ATTN_SMEM>>>(qhh, qhl, khh, khl, vhh, vhl, aoh, aol);
    // 11: output projection -> d_out
    gemm_mma<0><<<dim3(8, 128), 256, GSMEM>>>(aoh, aol, wph, wpl, bp, 1.f, out, 0, 0, 512, 0);
}